// round 2
// baseline (speedup 1.0000x reference)
#include <cuda_runtime.h>

#define BATCH    16
#define NTUP     65536
#define DSAMP    8
#define IN_SIZE  4096
#define OUT_SIZE 4096

// y[b*OUT_SIZE + o] = bias[o]
__global__ void hyper_init_kernel(const float* __restrict__ bias,
                                  float* __restrict__ y) {
    int i = blockIdx.x * blockDim.x + threadIdx.x;
    if (i < BATCH * OUT_SIZE) y[i] = bias[i & (OUT_SIZE - 1)];
}

__global__ __launch_bounds__(256)
void hyper_main_kernel(const float*  __restrict__ x,
                       const float2* __restrict__ means,
                       const float*  __restrict__ sigmas,
                       const float*  __restrict__ values,
                       const float4* __restrict__ noise,
                       float* __restrict__ y) {
    __shared__ float sx[IN_SIZE];

    // grid: (NTUP/256, BATCH); one tuple per thread
    const int b = blockIdx.y;

    // stage x[b] (16KB, L2-resident after first wave) into shared
    {
        const float4* xb4 = reinterpret_cast<const float4*>(x + b * IN_SIZE);
        float4* sx4 = reinterpret_cast<float4*>(sx);
        #pragma unroll
        for (int i = threadIdx.x; i < IN_SIZE / 4; i += 256)
            sx4[i] = xb4[i];
    }
    __syncthreads();

    float* __restrict__ yb = y + b * OUT_SIZE;
    const int n  = blockIdx.x * 256 + threadIdx.x;   // coalesced across warp
    const int bn = b * NTUP + n;

    const float2 mu  = means[bn];
    const float  sg  = sigmas[bn];
    const float  val = values[bn];

    // noise[b,n,:,:] = 16 floats = 4x float4
    const float4 nz0 = noise[bn * 4 + 0];
    const float4 nz1 = noise[bn * 4 + 1];
    const float4 nz2 = noise[bn * 4 + 2];
    const float4 nz3 = noise[bn * 4 + 3];

    const float nr[16] = { nz0.x, nz0.y, nz0.z, nz0.w,
                           nz1.x, nz1.y, nz1.z, nz1.w,
                           nz2.x, nz2.y, nz2.z, nz2.w,
                           nz3.x, nz3.y, nz3.z, nz3.w };

    // probs: sigma and the (2*pi*s2)^... denominator cancel in the
    // normalization over d, so probs depend only on the noise.
    float p[DSAMP];
    float psum = 0.0f;
    #pragma unroll
    for (int d = 0; d < DSAMP; d++) {
        const float a = nr[2 * d + 0];
        const float c = nr[2 * d + 1];
        p[d] = __expf(-0.5f * (a * a + c * c));
        psum += p[d];
    }
    const float scale = __fdividef(val, psum);

    // compute all addresses + weights first (pure ALU/FMA), then issue the
    // LDS-gather + RED burst with full ILP
    int   oi[DSAMP], ii[DSAMP];
    float w[DSAMP];
    #pragma unroll
    for (int d = 0; d < DSAMP; d++) {
        const float s0 = fmaf(nr[2 * d + 0], sg, mu.x);
        const float s1 = fmaf(nr[2 * d + 1], sg, mu.y);
        float f0 = rintf(s0);   // round-half-even == jnp.round
        float f1 = rintf(s1);
        f0 = fminf(fmaxf(f0, 0.0f), (float)(OUT_SIZE - 1));
        f1 = fminf(fmaxf(f1, 0.0f), (float)(IN_SIZE - 1));
        oi[d] = (int)f0;
        ii[d] = (int)f1;
        w[d]  = scale * p[d];
    }

    #pragma unroll
    for (int d = 0; d < DSAMP; d++) {
        atomicAdd(&yb[oi[d]], w[d] * sx[ii[d]]);  // no return use -> RED.ADD.F32
    }
}

extern "C" void kernel_launch(void* const* d_in, const int* in_sizes, int n_in,
                              void* d_out, int out_size) {
    const float*  x      = (const float*) d_in[0];  // [16, 4096]
    const float2* means  = (const float2*)d_in[1];  // [16, 65536, 2]
    const float*  sigmas = (const float*) d_in[2];  // [16, 65536]
    const float*  values = (const float*) d_in[3];  // [16, 65536]
    const float*  bias   = (const float*) d_in[4];  // [4096]
    const float4* noise  = (const float4*)d_in[5];  // [16, 65536, 8, 2]
    float* y = (float*)d_out;                       // [16, 4096]

    // init output with bias (d_out is poisoned before timing)
    hyper_init_kernel<<<(BATCH * OUT_SIZE + 255) / 256, 256>>>(bias, y);

    dim3 grid(NTUP / 256, BATCH);                   // (256, 16) = 4096 CTAs
    hyper_main_kernel<<<grid, 256>>>(x, means, sigmas, values, noise, y);
}

// round 3
// speedup vs baseline: 1.2547x; 1.2547x over previous
#include <cuda_runtime.h>

#define BATCH    16
#define NTUP     65536
#define DSAMP    8
#define IN_SIZE  4096
#define OUT_SIZE 4096
#define TPB      512
#define TPT      2

// y[b*OUT_SIZE + o] = bias[o]
__global__ void hyper_init_kernel(const float* __restrict__ bias,
                                  float* __restrict__ y) {
    int i = blockIdx.x * blockDim.x + threadIdx.x;
    if (i < BATCH * OUT_SIZE) y[i] = bias[i & (OUT_SIZE - 1)];
}

__global__ __launch_bounds__(TPB, 3)
void hyper_main_kernel(const float*  __restrict__ x,
                       const float2* __restrict__ means,
                       const float*  __restrict__ sigmas,
                       const float*  __restrict__ values,
                       const float4* __restrict__ noise,
                       float* __restrict__ y) {
    __shared__ float sx[IN_SIZE];

    const int b = blockIdx.y;

    // stage x[b] (16KB, L2-resident) into shared: 2 float4 per thread
    {
        const float4* xb4 = reinterpret_cast<const float4*>(x + b * IN_SIZE);
        float4* sx4 = reinterpret_cast<float4*>(sx);
        #pragma unroll
        for (int i = threadIdx.x; i < IN_SIZE / 4; i += TPB)
            sx4[i] = xb4[i];
    }
    __syncthreads();

    float* __restrict__ yb = y + b * OUT_SIZE;
    const int bn0  = b * NTUP;
    const int base = blockIdx.x * (TPB * TPT);

    #pragma unroll
    for (int it = 0; it < TPT; it++) {
        const int n  = base + it * TPB + threadIdx.x;   // coalesced
        const int bn = bn0 + n;

        const float2 mu  = means[bn];
        const float  sg  = sigmas[bn];
        const float  val = values[bn];

        const float4 nz0 = noise[bn * 4 + 0];
        const float4 nz1 = noise[bn * 4 + 1];
        const float4 nz2 = noise[bn * 4 + 2];
        const float4 nz3 = noise[bn * 4 + 3];

        const float nr[16] = { nz0.x, nz0.y, nz0.z, nz0.w,
                               nz1.x, nz1.y, nz1.z, nz1.w,
                               nz2.x, nz2.y, nz2.z, nz2.w,
                               nz3.x, nz3.y, nz3.z, nz3.w };

        // probs: sigma and the 2*pi*s2 denominator cancel in the
        // D-normalization, so probs depend only on the noise.
        float p[DSAMP];
        float psum = 0.0f;
        #pragma unroll
        for (int d = 0; d < DSAMP; d++) {
            const float a = nr[2 * d + 0];
            const float c = nr[2 * d + 1];
            p[d] = __expf(-0.5f * (a * a + c * c));
            psum += p[d];
        }
        const float scale = __fdividef(val, psum);

        // per sample: address math, LDS gather, fire-and-forget RED
        #pragma unroll
        for (int d = 0; d < DSAMP; d++) {
            const float s0 = fmaf(nr[2 * d + 0], sg, mu.x);
            const float s1 = fmaf(nr[2 * d + 1], sg, mu.y);
            float f0 = rintf(s0);   // round-half-even == jnp.round
            float f1 = rintf(s1);
            f0 = fminf(fmaxf(f0, 0.0f), (float)(OUT_SIZE - 1));
            f1 = fminf(fmaxf(f1, 0.0f), (float)(IN_SIZE - 1));
            const int oi = (int)f0;
            const int ii = (int)f1;
            atomicAdd(&yb[oi], (scale * p[d]) * sx[ii]);  // RED.ADD.F32
        }
    }
}

extern "C" void kernel_launch(void* const* d_in, const int* in_sizes, int n_in,
                              void* d_out, int out_size) {
    const float*  x      = (const float*) d_in[0];  // [16, 4096]
    const float2* means  = (const float2*)d_in[1];  // [16, 65536, 2]
    const float*  sigmas = (const float*) d_in[2];  // [16, 65536]
    const float*  values = (const float*) d_in[3];  // [16, 65536]
    const float*  bias   = (const float*) d_in[4];  // [4096]
    const float4* noise  = (const float4*)d_in[5];  // [16, 65536, 8, 2]
    float* y = (float*)d_out;                       // [16, 4096]

    hyper_init_kernel<<<(BATCH * OUT_SIZE + 255) / 256, 256>>>(bias, y);

    dim3 grid(NTUP / (TPB * TPT), BATCH);           // (64, 16) = 1024 CTAs
    hyper_main_kernel<<<grid, TPB>>>(x, means, sigmas, values, noise, y);
}

// round 4
// speedup vs baseline: 3.2479x; 2.5886x over previous
#include <cuda_runtime.h>

#define BATCH    16
#define NTUP     65536
#define DSAMP    8
#define IN_SIZE  4096
#define OUT_SIZE 4096
#define TPB      512
#define CPB      32              // CTAs per batch
#define TPT      (NTUP / (CPB * TPB))   // 4 tuples per thread

// y[b*OUT_SIZE + o] = bias[o]
__global__ void hyper_init_kernel(const float* __restrict__ bias,
                                  float* __restrict__ y) {
    int i = blockIdx.x * blockDim.x + threadIdx.x;
    if (i < BATCH * OUT_SIZE) y[i] = bias[i & (OUT_SIZE - 1)];
}

__global__ __launch_bounds__(TPB, 3)
void hyper_main_kernel(const float*  __restrict__ x,
                       const float2* __restrict__ means,
                       const float*  __restrict__ sigmas,
                       const float*  __restrict__ values,
                       const float4* __restrict__ noise,
                       float* __restrict__ y) {
    __shared__ float sx[IN_SIZE];
    __shared__ float sy[OUT_SIZE];   // per-CTA private accumulator

    const int b = blockIdx.y;

    // stage x[b] into shared + zero the private accumulator
    {
        const float4* xb4 = reinterpret_cast<const float4*>(x + b * IN_SIZE);
        float4* sx4 = reinterpret_cast<float4*>(sx);
        float4* sy4 = reinterpret_cast<float4*>(sy);
        const float4 z = make_float4(0.f, 0.f, 0.f, 0.f);
        #pragma unroll
        for (int i = threadIdx.x; i < IN_SIZE / 4; i += TPB) {
            sx4[i] = xb4[i];
            sy4[i] = z;
        }
    }
    __syncthreads();

    const int bn0  = b * NTUP;
    const int base = blockIdx.x * (TPB * TPT);

    #pragma unroll
    for (int it = 0; it < TPT; it++) {
        const int n  = base + it * TPB + threadIdx.x;   // coalesced
        const int bn = bn0 + n;

        const float2 mu  = means[bn];
        const float  sg  = sigmas[bn];
        const float  val = values[bn];

        const float4 nz0 = noise[bn * 4 + 0];
        const float4 nz1 = noise[bn * 4 + 1];
        const float4 nz2 = noise[bn * 4 + 2];
        const float4 nz3 = noise[bn * 4 + 3];

        const float nr[16] = { nz0.x, nz0.y, nz0.z, nz0.w,
                               nz1.x, nz1.y, nz1.z, nz1.w,
                               nz2.x, nz2.y, nz2.z, nz2.w,
                               nz3.x, nz3.y, nz3.z, nz3.w };

        // probs: sigma and the 2*pi*s2 denominator cancel in the
        // D-normalization, so probs depend only on the noise.
        float p[DSAMP];
        float psum = 0.0f;
        #pragma unroll
        for (int d = 0; d < DSAMP; d++) {
            const float a = nr[2 * d + 0];
            const float c = nr[2 * d + 1];
            p[d] = __expf(-0.5f * (a * a + c * c));
            psum += p[d];
        }
        const float scale = __fdividef(val, psum);

        // packed (oi,ii) keys + weights
        int   key[DSAMP];
        float w[DSAMP];
        #pragma unroll
        for (int d = 0; d < DSAMP; d++) {
            const float s0 = fmaf(nr[2 * d + 0], sg, mu.x);
            const float s1 = fmaf(nr[2 * d + 1], sg, mu.y);
            float f0 = rintf(s0);   // round-half-even == jnp.round
            float f1 = rintf(s1);
            f0 = fminf(fmaxf(f0, 0.0f), (float)(OUT_SIZE - 1));
            f1 = fminf(fmaxf(f1, 0.0f), (float)(IN_SIZE - 1));
            key[d] = ((int)f0 << 12) | (int)f1;
            w[d]   = scale * p[d];
        }

        // in-thread dedup: merge duplicate cells into first occurrence
        #pragma unroll
        for (int d = 1; d < DSAMP; d++) {
            const float wd = w[d];
            bool merged = false;
            #pragma unroll
            for (int j = 0; j < d; j++) {
                const bool eq = (!merged) && (key[d] == key[j]);
                if (eq) w[j] += wd;
                merged = merged || eq;
            }
            if (merged) w[d] = 0.0f;
        }

        // smem atomic accumulate (skip merged-away lanes)
        #pragma unroll
        for (int d = 0; d < DSAMP; d++) {
            if (w[d] != 0.0f) {
                const int oi = key[d] >> 12;
                const int ii = key[d] & (IN_SIZE - 1);
                atomicAdd(&sy[oi], w[d] * sx[ii]);
            }
        }
    }

    __syncthreads();

    // coalesced flush of the private accumulator into global y
    float* __restrict__ yb = y + b * OUT_SIZE;
    #pragma unroll
    for (int i = threadIdx.x; i < OUT_SIZE; i += TPB)
        atomicAdd(&yb[i], sy[i]);   // contiguous lanes -> sector-merged RED
}

extern "C" void kernel_launch(void* const* d_in, const int* in_sizes, int n_in,
                              void* d_out, int out_size) {
    const float*  x      = (const float*) d_in[0];  // [16, 4096]
    const float2* means  = (const float2*)d_in[1];  // [16, 65536, 2]
    const float*  sigmas = (const float*) d_in[2];  // [16, 65536]
    const float*  values = (const float*) d_in[3];  // [16, 65536]
    const float*  bias   = (const float*) d_in[4];  // [4096]
    const float4* noise  = (const float4*)d_in[5];  // [16, 65536, 8, 2]
    float* y = (float*)d_out;                       // [16, 4096]

    hyper_init_kernel<<<(BATCH * OUT_SIZE + 255) / 256, 256>>>(bias, y);

    dim3 grid(CPB, BATCH);                          // (32, 16) = 512 CTAs
    hyper_main_kernel<<<grid, TPB>>>(x, means, sigmas, values, noise, y);
}

// round 5
// speedup vs baseline: 3.4075x; 1.0491x over previous
#include <cuda_runtime.h>

#define BATCH    16
#define NTUP     65536
#define DSAMP    8
#define IN_SIZE  4096
#define OUT_SIZE 4096
#define TPB      512
#define GRID_MAIN 444            // 148 SMs x 3 CTAs: exactly one resident wave

// y[b*OUT_SIZE + o] = bias[o]
__global__ void hyper_init_kernel(const float* __restrict__ bias,
                                  float* __restrict__ y) {
    int i = blockIdx.x * blockDim.x + threadIdx.x;
    if (i < BATCH * OUT_SIZE) y[i] = bias[i & (OUT_SIZE - 1)];
}

__global__ __launch_bounds__(TPB, 3)
void hyper_main_kernel(const float*  __restrict__ x,
                       const float2* __restrict__ means,
                       const float*  __restrict__ sigmas,
                       const float*  __restrict__ values,
                       const float4* __restrict__ noise,
                       float* __restrict__ y) {
    __shared__ float sx[IN_SIZE];
    __shared__ float sy[OUT_SIZE];   // per-CTA private accumulator

    // 444 CTAs over 16 batches: batches 0..11 get 28 CTAs, 12..15 get 27.
    const int b   = blockIdx.x & 15;       // batch
    const int r   = blockIdx.x >> 4;       // rank within batch (0..27)
    const int C_b = 27 + (b < 12 ? 1 : 0); // CTAs serving this batch

    // stage x[b] into shared + zero the private accumulator
    {
        const float4* xb4 = reinterpret_cast<const float4*>(x + b * IN_SIZE);
        float4* sx4 = reinterpret_cast<float4*>(sx);
        float4* sy4 = reinterpret_cast<float4*>(sy);
        const float4 z = make_float4(0.f, 0.f, 0.f, 0.f);
        #pragma unroll
        for (int i = threadIdx.x; i < IN_SIZE / 4; i += TPB) {
            sx4[i] = xb4[i];
            sy4[i] = z;
        }
    }
    __syncthreads();

    const int bn0    = b * NTUP;
    const int stride = C_b * TPB;

    for (int n = r * TPB + threadIdx.x; n < NTUP; n += stride) {
        const int bn = bn0 + n;

        const float2 mu  = means[bn];
        const float  sg  = sigmas[bn];
        const float  val = values[bn];

        const float4 nz0 = noise[bn * 4 + 0];
        const float4 nz1 = noise[bn * 4 + 1];
        const float4 nz2 = noise[bn * 4 + 2];
        const float4 nz3 = noise[bn * 4 + 3];

        const float nr[16] = { nz0.x, nz0.y, nz0.z, nz0.w,
                               nz1.x, nz1.y, nz1.z, nz1.w,
                               nz2.x, nz2.y, nz2.z, nz2.w,
                               nz3.x, nz3.y, nz3.z, nz3.w };

        // probs: sigma and the 2*pi*s2 denominator cancel in the
        // D-normalization, so probs depend only on the noise.
        float p[DSAMP];
        float psum = 0.0f;
        #pragma unroll
        for (int d = 0; d < DSAMP; d++) {
            const float a = nr[2 * d + 0];
            const float c = nr[2 * d + 1];
            p[d] = __expf(-0.5f * (a * a + c * c));
            psum += p[d];
        }
        const float scale = __fdividef(val, psum);

        // packed (oi,ii) keys + weights
        int   key[DSAMP];
        float w[DSAMP];
        #pragma unroll
        for (int d = 0; d < DSAMP; d++) {
            const float s0 = fmaf(nr[2 * d + 0], sg, mu.x);
            const float s1 = fmaf(nr[2 * d + 1], sg, mu.y);
            float f0 = rintf(s0);   // round-half-even == jnp.round
            float f1 = rintf(s1);
            f0 = fminf(fmaxf(f0, 0.0f), (float)(OUT_SIZE - 1));
            f1 = fminf(fmaxf(f1, 0.0f), (float)(IN_SIZE - 1));
            key[d] = ((int)f0 << 12) | (int)f1;
            w[d]   = scale * p[d];
        }

        // in-thread dedup: merge duplicate cells into first occurrence
        #pragma unroll
        for (int d = 1; d < DSAMP; d++) {
            const float wd = w[d];
            bool merged = false;
            #pragma unroll
            for (int j = 0; j < d; j++) {
                const bool eq = (!merged) && (key[d] == key[j]);
                if (eq) w[j] += wd;
                merged = merged || eq;
            }
            if (merged) w[d] = 0.0f;
        }

        // smem atomic accumulate (skip merged-away lanes)
        #pragma unroll
        for (int d = 0; d < DSAMP; d++) {
            if (w[d] != 0.0f) {
                const int oi = key[d] >> 12;
                const int ii = key[d] & (IN_SIZE - 1);
                atomicAdd(&sy[oi], w[d] * sx[ii]);
            }
        }
    }

    __syncthreads();

    // coalesced, vectorized flush of the private accumulator into global y
    {
        const float2* sy2 = reinterpret_cast<const float2*>(sy);
        float2* yb2 = reinterpret_cast<float2*>(y + b * OUT_SIZE);
        #pragma unroll
        for (int i = threadIdx.x; i < OUT_SIZE / 2; i += TPB) {
            const float2 v = sy2[i];
            asm volatile("red.global.add.v2.f32 [%0], {%1, %2};"
                         :: "l"(yb2 + i), "f"(v.x), "f"(v.y) : "memory");
        }
    }
}

extern "C" void kernel_launch(void* const* d_in, const int* in_sizes, int n_in,
                              void* d_out, int out_size) {
    const float*  x      = (const float*) d_in[0];  // [16, 4096]
    const float2* means  = (const float2*)d_in[1];  // [16, 65536, 2]
    const float*  sigmas = (const float*) d_in[2];  // [16, 65536]
    const float*  values = (const float*) d_in[3];  // [16, 65536]
    const float*  bias   = (const float*) d_in[4];  // [4096]
    const float4* noise  = (const float4*)d_in[5];  // [16, 65536, 8, 2]
    float* y = (float*)d_out;                       // [16, 4096]

    hyper_init_kernel<<<(BATCH * OUT_SIZE + 255) / 256, 256>>>(bias, y);

    hyper_main_kernel<<<GRID_MAIN, TPB>>>(x, means, sigmas, values, noise, y);
}

// round 8
// speedup vs baseline: 3.5982x; 1.0560x over previous
#include <cuda_runtime.h>

#define BATCH    16
#define NTUP     65536
#define DSAMP    8
#define IN_SIZE  4096
#define OUT_SIZE 4096
#define TPB      512
#define GRID_MAIN 444            // 148 SMs x 3 CTAs: one resident wave

// y[b*OUT_SIZE + o] = bias[o]
__global__ void hyper_init_kernel(const float* __restrict__ bias,
                                  float* __restrict__ y) {
    int i = blockIdx.x * blockDim.x + threadIdx.x;
    if (i < BATCH * OUT_SIZE) y[i] = bias[i & (OUT_SIZE - 1)];
}

__global__ __launch_bounds__(TPB, 3)
void hyper_main_kernel(const float*  __restrict__ x,
                       const float2* __restrict__ means,
                       const float*  __restrict__ sigmas,
                       const float*  __restrict__ values,
                       const float4* __restrict__ noise,
                       float* __restrict__ y) {
    __shared__ float sx[IN_SIZE];
    __shared__ float sy[OUT_SIZE];   // per-CTA private accumulator

    // 444 CTAs over 16 batches: batches 0..11 get 28 CTAs, 12..15 get 27.
    const int b   = blockIdx.x & 15;       // batch
    const int r   = blockIdx.x >> 4;       // rank within batch (0..27)
    const int C_b = 27 + (b < 12 ? 1 : 0); // CTAs serving this batch

    // stage x[b] into shared + zero the private accumulator
    {
        const float4* xb4 = reinterpret_cast<const float4*>(x + b * IN_SIZE);
        float4* sx4 = reinterpret_cast<float4*>(sx);
        float4* sy4 = reinterpret_cast<float4*>(sy);
        const float4 z = make_float4(0.f, 0.f, 0.f, 0.f);
        #pragma unroll
        for (int i = threadIdx.x; i < IN_SIZE / 4; i += TPB) {
            sx4[i] = xb4[i];
            sy4[i] = z;
        }
    }
    __syncthreads();

    const int bn0    = b * NTUP;
    const int stride = C_b * TPB;

    for (int n = r * TPB + threadIdx.x; n < NTUP; n += stride) {
        const int bn = bn0 + n;

        const float2 mu  = means[bn];
        const float  sg  = sigmas[bn];
        const float  val = values[bn];

        const float4 nz0 = noise[bn * 4 + 0];
        const float4 nz1 = noise[bn * 4 + 1];
        const float4 nz2 = noise[bn * 4 + 2];
        const float4 nz3 = noise[bn * 4 + 3];

        const float nr[16] = { nz0.x, nz0.y, nz0.z, nz0.w,
                               nz1.x, nz1.y, nz1.z, nz1.w,
                               nz2.x, nz2.y, nz2.z, nz2.w,
                               nz3.x, nz3.y, nz3.z, nz3.w };

        // probs: sigma and the 2*pi*s2 denominator cancel in the
        // D-normalization, so probs depend only on the noise.
        float p[DSAMP];
        float psum = 0.0f;
        #pragma unroll
        for (int d = 0; d < DSAMP; d++) {
            const float a = nr[2 * d + 0];
            const float c = nr[2 * d + 1];
            p[d] = __expf(-0.5f * (a * a + c * c));
            psum += p[d];
        }
        const float scale = __fdividef(val, psum);

        // per-sample contribution = w * sx[ii]; keep oi for the scatter
        int   oi[DSAMP];
        float contrib[DSAMP];
        #pragma unroll
        for (int d = 0; d < DSAMP; d++) {
            const float s0 = fmaf(nr[2 * d + 0], sg, mu.x);
            const float s1 = fmaf(nr[2 * d + 1], sg, mu.y);
            float f0 = rintf(s0);   // round-half-even == jnp.round
            float f1 = rintf(s1);
            f0 = fminf(fmaxf(f0, 0.0f), (float)(OUT_SIZE - 1));
            f1 = fminf(fmaxf(f1, 0.0f), (float)(IN_SIZE - 1));
            oi[d] = (int)f0;
            contrib[d] = (scale * p[d]) * sx[(int)f1];
        }

        // merge all samples sharing the same output row: one ATOMS per
        // distinct oi (samples cluster within +-3 sigma, so merges are common)
        #pragma unroll
        for (int d = 1; d < DSAMP; d++) {
            const float cd = contrib[d];
            bool merged = false;
            #pragma unroll
            for (int j = 0; j < d; j++) {
                const bool eq = (!merged) && (oi[d] == oi[j]);
                if (eq) contrib[j] += cd;
                merged = merged || eq;
            }
            if (merged) oi[d] = -1;
        }

        #pragma unroll
        for (int d = 0; d < DSAMP; d++) {
            if (oi[d] >= 0)
                atomicAdd(&sy[oi[d]], contrib[d]);
        }
    }

    __syncthreads();

    // coalesced, vectorized flush of the private accumulator into global y
    {
        const float2* sy2 = reinterpret_cast<const float2*>(sy);
        float2* yb2 = reinterpret_cast<float2*>(y + b * OUT_SIZE);
        #pragma unroll
        for (int i = threadIdx.x; i < OUT_SIZE / 2; i += TPB) {
            const float2 v = sy2[i];
            asm volatile("red.global.add.v2.f32 [%0], {%1, %2};"
                         :: "l"(yb2 + i), "f"(v.x), "f"(v.y) : "memory");
        }
    }
}

extern "C" void kernel_launch(void* const* d_in, const int* in_sizes, int n_in,
                              void* d_out, int out_size) {
    const float*  x      = (const float*) d_in[0];  // [16, 4096]
    const float2* means  = (const float2*)d_in[1];  // [16, 65536, 2]
    const float*  sigmas = (const float*) d_in[2];  // [16, 65536]
    const float*  values = (const float*) d_in[3];  // [16, 65536]
    const float*  bias   = (const float*) d_in[4];  // [4096]
    const float4* noise  = (const float4*)d_in[5];  // [16, 65536, 8, 2]
    float* y = (float*)d_out;                       // [16, 4096]

    hyper_init_kernel<<<(BATCH * OUT_SIZE + 255) / 256, 256>>>(bias, y);

    hyper_main_kernel<<<GRID_MAIN, TPB>>>(x, means, sigmas, values, noise, y);
}

// round 9
// speedup vs baseline: 4.1759x; 1.1606x over previous
#include <cuda_runtime.h>

#define BATCH    16
#define NTUP     65536
#define IN_SIZE  4096
#define OUT_SIZE 4096
#define TPB      512
#define CPB      37                      // CTAs per batch
#define GRID_MAIN (BATCH * CPB)          // 592 = 148 SMs x 4 CTAs: one wave

// y[b*OUT_SIZE + o] = bias[o]
__global__ void hyper_init_kernel(const float* __restrict__ bias,
                                  float* __restrict__ y) {
    int i = blockIdx.x * blockDim.x + threadIdx.x;
    if (i < BATCH * OUT_SIZE) y[i] = bias[i & (OUT_SIZE - 1)];
}

__global__ __launch_bounds__(TPB, 4)
void hyper_main_kernel(const float*  __restrict__ x,
                       const float2* __restrict__ means,
                       const float*  __restrict__ sigmas,
                       const float*  __restrict__ values,
                       const float4* __restrict__ noise,
                       float* __restrict__ y) {
    __shared__ float sx[IN_SIZE];
    __shared__ float sy[OUT_SIZE];   // per-CTA private accumulator

    const int b = blockIdx.x & 15;   // batch
    const int r = blockIdx.x >> 4;   // rank within batch (0..36)

    // stage x[b] into shared + zero the private accumulator
    {
        const float4* xb4 = reinterpret_cast<const float4*>(x + b * IN_SIZE);
        float4* sx4 = reinterpret_cast<float4*>(sx);
        float4* sy4 = reinterpret_cast<float4*>(sy);
        const float4 z = make_float4(0.f, 0.f, 0.f, 0.f);
        #pragma unroll
        for (int i = threadIdx.x; i < IN_SIZE / 4; i += TPB) {
            sx4[i] = xb4[i];
            sy4[i] = z;
        }
    }
    __syncthreads();

    // two adjacent lanes share one tuple; each lane owns 4 of the 8 samples
    const int h      = threadIdx.x & 1;          // half selector
    const int bn0    = b * NTUP;
    const int stride = CPB * (TPB / 2);
    
    for (int t = r * (TPB / 2) + (threadIdx.x >> 1); t < NTUP; t += stride) {
        const int bn = bn0 + t;

        const float2 mu  = means[bn];    // pair-duplicated, sector-shared
        const float  sg  = sigmas[bn];
        const float  val = values[bn];

        // this lane's 8 noise floats (consecutive tids -> contiguous float4s)
        const float4 nza = noise[bn * 4 + 2 * h + 0];
        const float4 nzb = noise[bn * 4 + 2 * h + 1];
        const float nr[8] = { nza.x, nza.y, nza.z, nza.w,
                              nzb.x, nzb.y, nzb.z, nzb.w };

        // probs: sigma and the 2*pi*s2 denominator cancel in the
        // D-normalization, so probs depend only on the noise.
        float p[4];
        float psum = 0.0f;
        #pragma unroll
        for (int d = 0; d < 4; d++) {
            const float a = nr[2 * d + 0];
            const float c = nr[2 * d + 1];
            p[d] = __expf(-0.5f * (a * a + c * c));
            psum += p[d];
        }
        // combine the two half-sums across the lane pair
        psum += __shfl_xor_sync(0xffffffffu, psum, 1);
        const float scale = __fdividef(val, psum);

        // 4 samples: address math + gather
        int   oi[4];
        float contrib[4];
        #pragma unroll
        for (int d = 0; d < 4; d++) {
            const float s0 = fmaf(nr[2 * d + 0], sg, mu.x);
            const float s1 = fmaf(nr[2 * d + 1], sg, mu.y);
            float f0 = rintf(s0);   // round-half-even == jnp.round
            float f1 = rintf(s1);
            f0 = fminf(fmaxf(f0, 0.0f), (float)(OUT_SIZE - 1));
            f1 = fminf(fmaxf(f1, 0.0f), (float)(IN_SIZE - 1));
            oi[d] = (int)f0;
            contrib[d] = (scale * p[d]) * sx[(int)f1];
        }

        // merge samples sharing an output row (within this lane's half)
        #pragma unroll
        for (int d = 1; d < 4; d++) {
            const float cd = contrib[d];
            bool merged = false;
            #pragma unroll
            for (int j = 0; j < d; j++) {
                const bool eq = (!merged) && (oi[d] == oi[j]);
                if (eq) contrib[j] += cd;
                merged = merged || eq;
            }
            if (merged) oi[d] = -1;
        }

        #pragma unroll
        for (int d = 0; d < 4; d++) {
            if (oi[d] >= 0)
                atomicAdd(&sy[oi[d]], contrib[d]);
        }
    }

    __syncthreads();

    // coalesced, vectorized flush of the private accumulator into global y
    {
        const float4* sy4 = reinterpret_cast<const float4*>(sy);
        float4* yb4 = reinterpret_cast<float4*>(y + b * OUT_SIZE);
        #pragma unroll
        for (int i = threadIdx.x; i < OUT_SIZE / 4; i += TPB) {
            const float4 v = sy4[i];
            asm volatile("red.global.add.v4.f32 [%0], {%1, %2, %3, %4};"
                         :: "l"(yb4 + i), "f"(v.x), "f"(v.y), "f"(v.z), "f"(v.w)
                         : "memory");
        }
    }
}

extern "C" void kernel_launch(void* const* d_in, const int* in_sizes, int n_in,
                              void* d_out, int out_size) {
    const float*  x      = (const float*) d_in[0];  // [16, 4096]
    const float2* means  = (const float2*)d_in[1];  // [16, 65536, 2]
    const float*  sigmas = (const float*) d_in[2];  // [16, 65536]
    const float*  values = (const float*) d_in[3];  // [16, 65536]
    const float*  bias   = (const float*) d_in[4];  // [4096]
    const float4* noise  = (const float4*)d_in[5];  // [16, 65536, 8, 2]
    float* y = (float*)d_out;                       // [16, 4096]

    hyper_init_kernel<<<(BATCH * OUT_SIZE + 255) / 256, 256>>>(bias, y);

    hyper_main_kernel<<<GRID_MAIN, TPB>>>(x, means, sigmas, values, noise, y);
}